// round 8
// baseline (speedup 1.0000x reference)
#include <cuda_runtime.h>
#include <stdint.h>
#include <math.h>

#define IC 1024
#define OC 512
#define HH 64
#define WWW 64
#define NB 2
#define NA 16384
#define PRE_NMS_K 6000
#define POST_NMS_K 300

// ---- mma conv params ----
#define NKK8 1152                 // K/8 = 9216/8 (tap-major: t*1024+ic)
#define NITER 288                 // K stages of 32 (9 taps x 32 ic-chunks)
#define STAGE_BYTES 104448        // A 49152 + B 55296
#define B_OFF 49152
#define CONV_SMEM (2 * STAGE_BYTES)   // 208896

// ---- ffma2 fallback conv params (round-3 validated) ----
#define ICC 8
#define OCT 32
#define HT 4
#define IPITCH 68
#define WNUM (ICC*9*OCT)
#define INUM (ICC*6*IPITCH)
#define NCHUNK (IC/ICC)
#define NOCT (OC/OCT)

// ---------------- scratch (static device allocations, allowed) ----------------
__device__ float g_x[NB * OC * HH * WWW];
__device__ float g_wtc[4 * NKK8 * 3 * 8 * 32 * 4];
__device__ float g_xs3[NB * 66 * 66 * 3 * 1024];
__device__ float g_wr[NCHUNK * NOCT * WNUM];
__device__ float g_ipad[NB * IC * 66 * IPITCH];
__device__ float g_scores[NB * NA];
__device__ float4 g_boxes[NB * NA];
__device__ int   g_flag;

__device__ __forceinline__ unsigned ordkey(float f) {
    unsigned u = __float_as_uint(f);
    return (u & 0x80000000u) ? ~u : (u | 0x80000000u);
}
#define ORD_NEG_INF 0x007FFFFFu

__device__ __forceinline__ float to_tf32(float v) {
    float r;
    asm("cvt.rna.tf32.f32 %0, %1;" : "=f"(r) : "f"(v));
    return r;
}

#define MMA_TF32(c, a, b) \
    asm volatile("mma.sync.aligned.m16n8k8.row.col.f32.tf32.tf32.f32 " \
        "{%0,%1,%2,%3}, {%4,%5,%6,%7}, {%8,%9}, {%0,%1,%2,%3};" \
        : "+f"((c)[0]), "+f"((c)[1]), "+f"((c)[2]), "+f"((c)[3]) \
        : "r"((a).x), "r"((a).y), "r"((a).z), "r"((a).w), \
          "r"((b)[0]), "r"((b)[1]))

// ---- packed f32x2 helpers (fallback conv) ----
__device__ __forceinline__ unsigned long long bc2(float f) {
    unsigned long long r; unsigned u = __float_as_uint(f);
    asm("mov.b64 %0, {%1, %1};" : "=l"(r) : "r"(u));
    return r;
}
#define FMA2(d, a, b, c) \
    asm("fma.rn.f32x2 %0, %1, %2, %3;" : "=l"(d) : "l"(a), "l"(b), "l"(c))
__device__ __forceinline__ float lo32(unsigned long long v) {
    return __uint_as_float((unsigned)v);
}
__device__ __forceinline__ float hi32(unsigned long long v) {
    return __uint_as_float((unsigned)(v >> 32));
}

__global__ void zero_flag_kernel() { g_flag = 0; }

// ======================= mma path pre-passes ==================================
__global__ __launch_bounds__(256) void prep_w_tc(const float* __restrict__ Wc)
{
    int idx = blockIdx.x * 256 + threadIdx.x;
    if (idx >= 4 * NKK8 * 8 * 32 * 4) return;
    int r   = idx & 3;
    int lam = (idx >> 2) & 31;
    int mf  = (idx >> 7) & 7;
    int rest = idx >> 10;
    int kk8 = rest % NKK8;
    int mt  = rest / NKK8;
    int oc = mt * 128 + mf * 16 + (lam >> 2) + (r & 1) * 8;
    int t  = kk8 / 128;
    int ic = (kk8 % 128) * 8 + (lam & 3) + (r >> 1) * 4;
    float v  = Wc[((size_t)oc * IC + ic) * 9 + t];
    float a0 = to_tf32(v);
    float r1 = v - a0;
    float a1 = to_tf32(r1);
    float a2 = to_tf32(r1 - a1);
    size_t base = (size_t)(mt * NKK8 + kk8) * 3072 + mf * 128 + lam * 4 + r;
    g_wtc[base]        = a0;
    g_wtc[base + 1024] = a1;
    g_wtc[base + 2048] = a2;
}

__global__ __launch_bounds__(256) void prep_x_tc(const float* __restrict__ in)
{
    int idx = blockIdx.x * 256 + threadIdx.x;
    if (idx >= NB * 66 * 66 * 1024) return;
    int ic = idx & 1023;
    int pix = idx >> 10;
    int pc = pix % 66;
    int rest2 = pix / 66;
    int pr = rest2 % 66;
    int b  = rest2 / 66;
    int h = pr - 1, w = pc - 1;
    float v = 0.f;
    if (h >= 0 && h < HH && w >= 0 && w < WWW)
        v = in[(((size_t)b * IC + ic) * HH + h) * WWW + w];
    float a0 = to_tf32(v);
    float r1 = v - a0;
    float a1 = to_tf32(r1);
    float a2 = to_tf32(r1 - a1);
    size_t base = (size_t)pix * 3072 + ic;
    g_xs3[base]        = a0;
    g_xs3[base + 1024] = a1;
    g_xs3[base + 2048] = a2;
}

// ====================== mma conv (under test) =================================
__global__ __launch_bounds__(256, 1) void conv_mma_kernel(const float* __restrict__ bc)
{
    extern __shared__ char smem[];
    const int tid  = threadIdx.x;
    const int wid  = tid >> 5;
    const int lane = tid & 31;
    const int mt = blockIdx.x;
    const int nt = blockIdx.y;
    const int b  = blockIdx.z;
    const int h0 = nt * 2;
    const int wm = wid & 1;
    const int wn = wid >> 1;

    float acc[4][4][4];
#pragma unroll
    for (int i = 0; i < 4; i++)
#pragma unroll
        for (int j = 0; j < 4; j++)
#pragma unroll
            for (int r = 0; r < 4; r++) acc[i][j][r] = 0.f;

    const char*  wsrc = (const char*)(g_wtc + (size_t)mt * NKK8 * 3072);
    const float* xb   = g_xs3 + (size_t)b * 66 * 66 * 3072;

    int bl_n[12], bl_u[12], bl_s[12];
#pragma unroll
    for (int j = 0; j < 12; j++) {
        int id = tid + j * 256;
        bl_s[j] = id >> 10;
        bl_n[j] = (id >> 3) & 127;
        bl_u[j] = id & 7;
    }

    auto issue = [&](int i, int st) {
        char* sa = smem + st * STAGE_BYTES;
        const char* asrc = wsrc + (size_t)i * 49152;
        unsigned au = (unsigned)__cvta_generic_to_shared(sa);
#pragma unroll
        for (int j = 0; j < 12; j++) {
            int off = (tid + j * 256) * 16;
            asm volatile("cp.async.cg.shared.global [%0], [%1], 16;"
                         :: "r"(au + off), "l"(asrc + off));
        }
        int t = i >> 5, c32 = i & 31;
        int kh = t / 3, kw = t - kh * 3;
        unsigned bu = au + B_OFF;
#pragma unroll
        for (int j = 0; j < 12; j++) {
            int n = bl_n[j];
            int pr = h0 + (n >> 6) + kh;
            int pc = (n & 63) + kw;
            const float* src = xb + (size_t)(pr * 66 + pc) * 3072 + (bl_s[j] << 10)
                                  + (c32 << 5) + (bl_u[j] << 2);
            unsigned dst = bu + bl_s[j] * 18432 + n * 144 + bl_u[j] * 16;
            asm volatile("cp.async.cg.shared.global [%0], [%1], 16;"
                         :: "r"(dst), "l"(src));
        }
        asm volatile("cp.async.commit_group;");
    };

    issue(0, 0);

    for (int i = 0; i < NITER; i++) {
        const int st = i & 1;
        if (i + 1 < NITER) {
            issue(i + 1, st ^ 1);
            asm volatile("cp.async.wait_group 1;");
        } else {
            asm volatile("cp.async.wait_group 0;");
        }
        __syncthreads();

        const char* sa = smem + st * STAGE_BYTES;
#pragma unroll
        for (int kk8 = 0; kk8 < 4; kk8++) {
            uint4 a[3][4];
#pragma unroll
            for (int s = 0; s < 3; s++)
#pragma unroll
                for (int mf = 0; mf < 4; mf++)
                    a[s][mf] = *(const uint4*)(sa +
                        (((kk8 * 3 + s) * 8 + (wm * 4 + mf)) * 512) + lane * 16);
            uint32_t bb[3][4][2];
#pragma unroll
            for (int s = 0; s < 3; s++)
#pragma unroll
                for (int nf = 0; nf < 4; nf++) {
                    const char* ba = sa + B_OFF + s * 18432
                        + (wn * 32 + nf * 8 + (lane >> 2)) * 144
                        + (kk8 * 8 + (lane & 3)) * 4;
                    bb[s][nf][0] = *(const uint32_t*)ba;
                    bb[s][nf][1] = *(const uint32_t*)(ba + 16);
                }
#pragma unroll
            for (int mf = 0; mf < 4; mf++)
#pragma unroll
                for (int nf = 0; nf < 4; nf++) {
                    MMA_TF32(acc[mf][nf], a[0][mf], bb[0][nf]);
                    MMA_TF32(acc[mf][nf], a[0][mf], bb[1][nf]);
                    MMA_TF32(acc[mf][nf], a[1][mf], bb[0][nf]);
                    MMA_TF32(acc[mf][nf], a[1][mf], bb[1][nf]);
                    MMA_TF32(acc[mf][nf], a[0][mf], bb[2][nf]);
                    MMA_TF32(acc[mf][nf], a[2][mf], bb[0][nf]);
                }
        }
        __syncthreads();
    }

#pragma unroll
    for (int mf = 0; mf < 4; mf++) {
        int oc0 = mt * 128 + wm * 64 + mf * 16 + (lane >> 2);
        float bias0 = bc[oc0];
        float bias8 = bc[oc0 + 8];
#pragma unroll
        for (int nf = 0; nf < 4; nf++) {
            int nl = wn * 32 + nf * 8 + (lane & 3) * 2;
            int h = h0 + (nl >> 6);
            int w = nl & 63;
            float2 v0, v1;
            v0.x = fmaxf(acc[mf][nf][0] + bias0, 0.f);
            v0.y = fmaxf(acc[mf][nf][1] + bias0, 0.f);
            v1.x = fmaxf(acc[mf][nf][2] + bias8, 0.f);
            v1.y = fmaxf(acc[mf][nf][3] + bias8, 0.f);
            *(float2*)(g_x + (((size_t)(b * OC + oc0) * HH + h) * WWW + w))     = v0;
            *(float2*)(g_x + (((size_t)(b * OC + oc0 + 8) * HH + h) * WWW + w)) = v1;
        }
    }
}

// ============ check kernel: sampled direct fp32 conv vs g_x ===================
// grid (512, 2): block = (oc, b); 128 threads = 16 pixels x 8 ic-slices.
__global__ __launch_bounds__(128) void check_kernel(
    const float* __restrict__ in, const float* __restrict__ Wc,
    const float* __restrict__ bc)
{
    __shared__ float part[128];
    const int oc = blockIdx.x, b = blockIdx.y, tid = threadIdx.x;
    const int p = tid & 15, slice = tid >> 4;
    const int hs[4] = {0, 1, 31, 63};
    const int ws[4] = {0, 1, 32, 63};
    const int h = hs[p >> 2], w = ws[p & 3];

    float s = 0.f;
    const float* wrow0 = Wc + (size_t)oc * IC * 9;
    for (int ic = slice * 128; ic < slice * 128 + 128; ic++) {
        const float* wrow = wrow0 + (size_t)ic * 9;
        const float* irow = in + ((size_t)(b * IC + ic) * HH) * WWW;
#pragma unroll
        for (int kh = 0; kh < 3; kh++) {
            int ih = h - 1 + kh;
            if (ih < 0 || ih >= HH) continue;
#pragma unroll
            for (int kw = 0; kw < 3; kw++) {
                int iw = w - 1 + kw;
                if (iw < 0 || iw >= WWW) continue;
                s += wrow[kh * 3 + kw] * irow[ih * WWW + iw];
            }
        }
    }
    part[tid] = s;
    __syncthreads();
    if (tid < 16) {
        float tot = 0.f;
        for (int sl = 0; sl < 8; sl++) tot += part[sl * 16 + tid];
        float v = fmaxf(tot + bc[oc], 0.f);
        float ref = g_x[(((size_t)(b * OC + oc) * HH) + h) * WWW + w];
        float rel = fabsf(v - ref) / fmaxf(fabsf(v), 1.0f);
        if (rel > 1e-4f) atomicOr(&g_flag, 1);
    }
}

// ================= fallback path (round-3 validated, gated) ===================
__global__ __launch_bounds__(256) void prep_weights(const float* __restrict__ Wc)
{
    if (g_flag == 0) return;
    int idx = blockIdx.x * 256 + threadIdx.x;
    if (idx >= NCHUNK * NOCT * WNUM) return;
    int c  = idx / (NOCT * WNUM);
    int r  = idx - c * (NOCT * WNUM);
    int ot = r / WNUM;
    int e  = r - ot * WNUM;
    int icl = e / 288;
    int e2  = e - icl * 288;
    int k   = e2 >> 5;
    int ocl = e2 & 31;
    g_wr[idx] = Wc[((size_t)(ot * 32 + ocl) * IC + c * ICC + icl) * 9 + k];
}

__global__ __launch_bounds__(256) void prep_input(const float* __restrict__ in)
{
    if (g_flag == 0) return;
    int idx = blockIdx.x * 256 + threadIdx.x;
    const int TOT = NB * IC * 66 * IPITCH;
    if (idx >= TOT) return;
    int bi  = idx / (66 * IPITCH);
    int r   = idx - bi * (66 * IPITCH);
    int row = r / IPITCH;
    int col = r - row * IPITCH;
    int h   = row - 1;
    int w   = col - 1;
    float v = 0.f;
    if (h >= 0 && h < HH && w >= 0 && w < WWW && col < 66)
        v = in[((size_t)bi * HH + h) * WWW + w];
    g_ipad[idx] = v;
}

__global__ __launch_bounds__(128, 3) void conv_ffma2_kernel(const float* __restrict__ bc)
{
    if (g_flag == 0) return;
    __shared__ float sW[2][WNUM];
    __shared__ float sIn[2][INUM];

    const int oc0 = blockIdx.x * OCT;
    const int h0  = blockIdx.y * HT;
    const int b   = blockIdx.z;
    const int tid = threadIdx.x;

    const int tz  = tid >> 5;
    const int to0 = ((tid >> 3) & 3) * 8;
    const int tw0 = (tid & 7) * 8;

    const unsigned sW_u[2] = {
        (unsigned)__cvta_generic_to_shared(&sW[0][0]),
        (unsigned)__cvta_generic_to_shared(&sW[1][0]) };
    const unsigned sIn_u[2] = {
        (unsigned)__cvta_generic_to_shared(&sIn[0][0]),
        (unsigned)__cvta_generic_to_shared(&sIn[1][0]) };

    const float* wbase = g_wr + (size_t)blockIdx.x * WNUM;
    int i_icl[7], i_off[7];
#pragma unroll
    for (int s = 0; s < 7; s++) {
        int idx4 = tid + s * 128;
        int icl  = idx4 / 102;
        int r    = idx4 - icl * 102;
        int row  = r / 17;
        int c4   = r - row * 17;
        i_icl[s] = icl;
        i_off[s] = (h0 + row) * IPITCH + c4 * 4;
    }

    unsigned long long acc2[4][8];
#pragma unroll
    for (int p = 0; p < 4; p++)
#pragma unroll
        for (int j = 0; j < 8; j++) acc2[p][j] = 0ull;

    auto issue_chunk = [&](int kc, int bu) {
        const unsigned sWu  = sW_u[bu];
        const unsigned sInu = sIn_u[bu];
        const float* ws = wbase + (size_t)kc * (NOCT * WNUM);
#pragma unroll
        for (int s = 0; s < 5; s++) {
            int idx4 = tid + s * 128;
            if (idx4 < WNUM / 4) {
                const float* g = ws + idx4 * 4;
                asm volatile("cp.async.cg.shared.global [%0], [%1], 16;"
                             :: "r"(sWu + (unsigned)(idx4 * 16)), "l"(g));
            }
        }
        const int ic0 = kc * ICC;
#pragma unroll
        for (int s = 0; s < 7; s++) {
            int idx4 = tid + s * 128;
            if (idx4 < INUM / 4) {
                const float* g = g_ipad +
                    ((size_t)(b * IC + ic0 + i_icl[s]) * 66) * IPITCH + i_off[s];
                asm volatile("cp.async.cg.shared.global [%0], [%1], 16;"
                             :: "r"(sInu + (unsigned)(idx4 * 16)), "l"(g));
            }
        }
        asm volatile("cp.async.commit_group;");
    };

    issue_chunk(0, 0);

    for (int kc = 0; kc < NCHUNK; kc++) {
        const int cur = kc & 1;
        if (kc < NCHUNK - 1) {
            issue_chunk(kc + 1, cur ^ 1);
            asm volatile("cp.async.wait_group 1;");
        } else {
            asm volatile("cp.async.wait_group 0;");
        }
        __syncthreads();

        const float* W_ = sW[cur];
        const float* I_ = sIn[cur];

#pragma unroll 1
        for (int ic = 0; ic < ICC; ic++) {
            const float* irow = I_ + (ic * 6 + tz) * IPITCH + tw0;
            const float* wrow = W_ + ic * 9 * OCT + to0;
#pragma unroll
            for (int kh = 0; kh < 3; kh++) {
                float4 f0 = *(const float4*)(irow + kh * IPITCH);
                float4 f1 = *(const float4*)(irow + kh * IPITCH + 4);
                float4 f2 = *(const float4*)(irow + kh * IPITCH + 8);
                unsigned long long ib[10];
                ib[0] = bc2(f0.x); ib[1] = bc2(f0.y); ib[2] = bc2(f0.z); ib[3] = bc2(f0.w);
                ib[4] = bc2(f1.x); ib[5] = bc2(f1.y); ib[6] = bc2(f1.z); ib[7] = bc2(f1.w);
                ib[8] = bc2(f2.x); ib[9] = bc2(f2.y);
#pragma unroll
                for (int kw = 0; kw < 3; kw++) {
                    const ulonglong2* wp =
                        (const ulonglong2*)(wrow + (kh * 3 + kw) * OCT);
                    ulonglong2 wa = wp[0];
                    ulonglong2 wb = wp[1];
#pragma unroll
                    for (int j = 0; j < 8; j++) {
                        FMA2(acc2[0][j], wa.x, ib[j + kw], acc2[0][j]);
                        FMA2(acc2[1][j], wa.y, ib[j + kw], acc2[1][j]);
                        FMA2(acc2[2][j], wb.x, ib[j + kw], acc2[2][j]);
                        FMA2(acc2[3][j], wb.y, ib[j + kw], acc2[3][j]);
                    }
                }
            }
        }
        __syncthreads();
    }

    const int h = h0 + tz;
#pragma unroll
    for (int p = 0; p < 4; p++) {
#pragma unroll
        for (int s = 0; s < 2; s++) {
            int oc = oc0 + to0 + 2 * p + s;
            float bias = bc[oc];
            float* op = &g_x[((size_t)(b * OC + oc) * HH + h) * WWW + tw0];
#pragma unroll
            for (int j = 0; j < 8; j++) {
                float v = (s == 0 ? lo32(acc2[p][j]) : hi32(acc2[p][j])) + bias;
                op[j] = v > 0.f ? v : 0.f;
            }
        }
    }
}

// ============ Kernel 2: heads (round-3 validated 64-thread version) ===========
__global__ __launch_bounds__(64) void heads_kernel(
    const float* __restrict__ meta,
    const float* __restrict__ Wcls, const float* __restrict__ bcls,
    const float* __restrict__ Wbb,  const float* __restrict__ bbb)
{
    __shared__ float sw[512 * 20];
    __shared__ float sb[20];

    const int h = blockIdx.x, b = blockIdx.y, tid = threadIdx.x;

    for (int idx = tid; idx < 512 * 20; idx += 64) {
        int c = idx / 20, o = idx - c * 20;
        sw[idx] = (o < 4) ? Wcls[o * 512 + c] : Wbb[(o - 4) * 512 + c];
    }
    if (tid < 20) sb[tid] = (tid < 4) ? bcls[tid] : bbb[tid - 4];
    __syncthreads();

    const int w = tid;
    float acc[20];
#pragma unroll
    for (int o = 0; o < 20; o++) acc[o] = 0.f;

    const float* xp = g_x + ((size_t)(b * OC) * HH + h) * WWW + w;
    for (int c = 0; c < 512; c++) {
        float xv = xp[(size_t)c * HH * WWW];
        const float4* wp = reinterpret_cast<const float4*>(&sw[c * 20]);
        float4 w0 = wp[0], w1 = wp[1], w2 = wp[2], w3 = wp[3], w4 = wp[4];
        acc[0]  = fmaf(xv, w0.x, acc[0]);  acc[1]  = fmaf(xv, w0.y, acc[1]);
        acc[2]  = fmaf(xv, w0.z, acc[2]);  acc[3]  = fmaf(xv, w0.w, acc[3]);
        acc[4]  = fmaf(xv, w1.x, acc[4]);  acc[5]  = fmaf(xv, w1.y, acc[5]);
        acc[6]  = fmaf(xv, w1.z, acc[6]);  acc[7]  = fmaf(xv, w1.w, acc[7]);
        acc[8]  = fmaf(xv, w2.x, acc[8]);  acc[9]  = fmaf(xv, w2.y, acc[9]);
        acc[10] = fmaf(xv, w2.z, acc[10]); acc[11] = fmaf(xv, w2.w, acc[11]);
        acc[12] = fmaf(xv, w3.x, acc[12]); acc[13] = fmaf(xv, w3.y, acc[13]);
        acc[14] = fmaf(xv, w3.z, acc[14]); acc[15] = fmaf(xv, w3.w, acc[15]);
        acc[16] = fmaf(xv, w4.x, acc[16]); acc[17] = fmaf(xv, w4.y, acc[17]);
        acc[18] = fmaf(xv, w4.z, acc[18]); acc[19] = fmaf(xv, w4.w, acc[19]);
    }

    float s[4];
#pragma unroll
    for (int a = 0; a < 4; a++) s[a] = acc[a] + sb[a];
    float prob[4];
#pragma unroll
    for (int a = 0; a < 4; a++) {
        int p = a ^ 2;
        float m  = fmaxf(s[a], s[p]);
        float ea = expf(s[a] - m);
        float eb = expf(s[p] - m);
        prob[a]  = ea / (ea + eb);
    }

    const float im_h = meta[b * 3 + 0];
    const float im_w = meta[b * 3 + 1];
    const float scl  = meta[b * 3 + 2];
    const float minsz = 16.f * scl;

    const int base = b * NA + (h * 64 + w) * 4;
#pragma unroll
    for (int a = 0; a < 4; a++) {
        float wa = (float)(64 << a);
        float cx = w * 16.f + 8.f;
        float cy = h * 16.f + 8.f;
        float d0 = acc[4 + a * 4 + 0] + sb[4 + a * 4 + 0];
        float d1 = acc[4 + a * 4 + 1] + sb[4 + a * 4 + 1];
        float d2 = acc[4 + a * 4 + 2] + sb[4 + a * 4 + 2];
        float d3 = acc[4 + a * 4 + 3] + sb[4 + a * 4 + 3];
        float pcx = d0 * wa + cx, pcy = d1 * wa + cy;
        float pw  = expf(d2) * wa, ph = expf(d3) * wa;
        float x1 = pcx - 0.5f * pw, y1 = pcy - 0.5f * ph;
        float x2 = pcx + 0.5f * pw, y2 = pcy + 0.5f * ph;
        x1 = fminf(fmaxf(x1, 0.f), im_w - 1.f);
        x2 = fminf(fmaxf(x2, 0.f), im_w - 1.f);
        y1 = fminf(fmaxf(y1, 0.f), im_h - 1.f);
        y2 = fminf(fmaxf(y2, 0.f), im_h - 1.f);
        bool keep = (x2 - x1 + 1.f >= minsz) && (y2 - y1 + 1.f >= minsz);
        g_scores[base + a] = keep ? prob[a] : -INFINITY;
        g_boxes[base + a]  = make_float4(x1, y1, x2, y2);
    }
}

// ================= Kernel 3: exact top-6000 mark (per image) ==================
__global__ __launch_bounds__(1024) void topk_kernel()
{
    const int b   = blockIdx.x;
    const int tid = threadIdx.x;
    float* scores = g_scores + b * NA;

    unsigned key[16];
    const int i0 = tid * 16;
#pragma unroll
    for (int i = 0; i < 16; i++) key[i] = ordkey(scores[i0 + i]);

    __shared__ int wsum[32];
    __shared__ int s_total;
    const int lane = tid & 31, wid = tid >> 5;

    auto count_ge = [&](unsigned cand) -> int {
        int local = 0;
#pragma unroll
        for (int i = 0; i < 16; i++) local += (key[i] >= cand) ? 1 : 0;
        for (int off = 16; off; off >>= 1)
            local += __shfl_down_sync(0xFFFFFFFFu, local, off);
        if (lane == 0) wsum[wid] = local;
        __syncthreads();
        if (tid == 0) {
            int st = 0;
            for (int k = 0; k < 32; k++) st += wsum[k];
            s_total = st;
        }
        __syncthreads();
        int r = s_total;
        __syncthreads();
        return r;
    };

    unsigned thr = 0;
    for (int bit = 31; bit >= 0; bit--) {
        unsigned cand = thr | (1u << bit);
        if (count_ge(cand) >= PRE_NMS_K) thr = cand;
    }
    const int n_gt = count_ge(thr + 1u);
    const int need = PRE_NMS_K - n_gt;

    int my_eq = 0;
#pragma unroll
    for (int i = 0; i < 16; i++) my_eq += (key[i] == thr) ? 1 : 0;

    int v = my_eq;
    for (int off = 1; off < 32; off <<= 1) {
        int tt = __shfl_up_sync(0xFFFFFFFFu, v, off);
        if (lane >= off) v += tt;
    }
    __syncthreads();
    if (lane == 31) wsum[wid] = v;
    __syncthreads();
    if (wid == 0) {
        int sv = wsum[lane];
        for (int off = 1; off < 32; off <<= 1) {
            int tt = __shfl_up_sync(0xFFFFFFFFu, sv, off);
            if (lane >= off) sv += tt;
        }
        wsum[lane] = sv;
    }
    __syncthreads();
    int rank = v - my_eq + (wid ? wsum[wid - 1] : 0);

#pragma unroll
    for (int i = 0; i < 16; i++) {
        if (key[i] == thr) {
            if (rank >= need) scores[i0 + i] = -INFINITY;
            rank++;
        } else if (key[i] < thr) {
            scores[i0 + i] = -INFINITY;
        }
    }
}

// ===================== Kernel 4: exact greedy NMS (per image) =================
__global__ __launch_bounds__(512) void nms_kernel(float* __restrict__ out)
{
    const int b   = blockIdx.x;
    const int tid = threadIdx.x;
    const float4* boxes = g_boxes + b * NA;

    float sc[32];
    const int i0 = tid * 32;
#pragma unroll
    for (int i = 0; i < 32; i++) sc[i] = g_scores[b * NA + i0 + i];

    __shared__ unsigned long long swm[16];
    __shared__ unsigned long long s_best;
    __shared__ float4 s_box;
    __shared__ float  s_area;
    __shared__ int    s_firstj;

    const int lane = tid & 31, wid = tid >> 5;

    for (int it = 0; it < POST_NMS_K; it++) {
        unsigned long long loc = ((unsigned long long)ORD_NEG_INF << 32);
#pragma unroll
        for (int i = 0; i < 32; i++) {
            unsigned long long kk =
                ((unsigned long long)ordkey(sc[i]) << 32) |
                (unsigned)(65535 - (i0 + i));
            loc = (kk > loc) ? kk : loc;
        }
        for (int off = 16; off; off >>= 1) {
            unsigned long long o = __shfl_down_sync(0xFFFFFFFFu, loc, off);
            loc = (o > loc) ? o : loc;
        }
        if (lane == 0) swm[wid] = loc;
        __syncthreads();
        if (tid < 16) {
            unsigned long long vv = swm[tid];
            for (int off = 8; off; off >>= 1) {
                unsigned long long o = __shfl_down_sync(0x0000FFFFu, vv, off);
                vv = (o > vv) ? o : vv;
            }
            if (tid == 0) s_best = vv;
        }
        __syncthreads();

        if (tid == 0) {
            unsigned long long best = s_best;
            unsigned keypart = (unsigned)(best >> 32);
            int j;
            if (keypart == ORD_NEG_INF && it > 0) j = s_firstj;
            else j = 65535 - (int)(best & 0xFFFFFFFFull);
            if (it == 0) s_firstj = j;
            float4 bx = boxes[j];
            s_box  = bx;
            s_area = (bx.z - bx.x + 1.f) * (bx.w - bx.y + 1.f);
            float* o = out + (size_t)(b * POST_NMS_K + it) * 5;
            o[0] = (float)b; o[1] = bx.x; o[2] = bx.y; o[3] = bx.z; o[4] = bx.w;
        }
        __syncthreads();

        const float4 jb = s_box;
        const float  ja = s_area;
#pragma unroll 4
        for (int i = 0; i < 32; i++) {
            float4 bb = boxes[i0 + i];
            float xx1 = fmaxf(jb.x, bb.x);
            float yy1 = fmaxf(jb.y, bb.y);
            float xx2 = fminf(jb.z, bb.z);
            float yy2 = fminf(jb.w, bb.w);
            float iw  = fmaxf(xx2 - xx1 + 1.f, 0.f);
            float ih  = fmaxf(yy2 - yy1 + 1.f, 0.f);
            float inter = iw * ih;
            float area  = (bb.z - bb.x + 1.f) * (bb.w - bb.y + 1.f);
            float iou   = inter / (ja + area - inter);
            if (iou > 0.7f) sc[i] = -INFINITY;
        }
    }
}

// ================================ launcher ====================================
extern "C" void kernel_launch(void* const* d_in, const int* in_sizes, int n_in,
                              void* d_out, int out_size)
{
    const float* feat = (const float*)d_in[0];
    const float* meta = (const float*)d_in[1];
    const float* Wc   = (const float*)d_in[3];
    const float* bc   = (const float*)d_in[4];
    const float* Wcls = (const float*)d_in[5];
    const float* bcls = (const float*)d_in[6];
    const float* Wbb  = (const float*)d_in[7];
    const float* bbb  = (const float*)d_in[8];
    float* out = (float*)d_out;

    cudaFuncSetAttribute(conv_mma_kernel,
                         cudaFuncAttributeMaxDynamicSharedMemorySize, CONV_SMEM);

    zero_flag_kernel<<<1, 1>>>();
    // --- mma path (under test) ---
    prep_w_tc<<<(4 * NKK8 * 1024 + 255) / 256, 256>>>(Wc);
    prep_x_tc<<<(NB * 66 * 66 * 1024 + 255) / 256, 256>>>(feat);
    conv_mma_kernel<<<dim3(4, 32, 2), 256, CONV_SMEM>>>(bc);
    // --- verify samples; set g_flag if mma conv is wrong ---
    check_kernel<<<dim3(512, 2), 128>>>(feat, Wc, bc);
    // --- validated fallback path (runs only if flag set) ---
    prep_weights<<<(NCHUNK * NOCT * WNUM + 255) / 256, 256>>>(Wc);
    prep_input<<<(NB * IC * 66 * IPITCH + 255) / 256, 256>>>(feat);
    conv_ffma2_kernel<<<dim3(16, 16, 2), 128>>>(bc);
    // --- validated tail ---
    heads_kernel<<<dim3(64, 2), 64>>>(meta, Wcls, bcls, Wbb, bbb);
    topk_kernel<<<2, 1024>>>();
    nms_kernel<<<2, 512>>>(out);
}

// round 9
// speedup vs baseline: 1.0053x; 1.0053x over previous
#include <cuda_runtime.h>
#include <stdint.h>
#include <math.h>

#define IC 1024
#define OC 512
#define HH 64
#define WWW 64
#define NB 2
#define NA 16384
#define PRE_NMS_K 6000
#define POST_NMS_K 300

// ---- mma conv params ----
#define NKK8 1152                 // K/8 = 9216/8 (tap-major: t*1024+ic)
#define NITER 288                 // K stages of 32 (9 taps x 32 ic-chunks)
#define STAGE_BYTES 104448        // A 49152 + B 55296
#define B_OFF 49152
#define CONV_SMEM (2 * STAGE_BYTES)   // 208896

// ---- ffma2 fallback conv params (round-3 validated) ----
#define ICC 8
#define OCT 32
#define HT 4
#define IPITCH 68
#define WNUM (ICC*9*OCT)
#define INUM (ICC*6*IPITCH)
#define NCHUNK (IC/ICC)
#define NOCT (OC/OCT)

// ---------------- scratch (static device allocations, allowed) ----------------
__device__ float g_x[NB * OC * HH * WWW];
__device__ float g_wtc[4 * NKK8 * 3 * 8 * 32 * 4];
__device__ float g_xs3[NB * 66 * 66 * 3 * 1024];
__device__ float g_wr[NCHUNK * NOCT * WNUM];
__device__ float g_ipad[NB * IC * 66 * IPITCH];
__device__ float g_scores[NB * NA];
__device__ float4 g_boxes[NB * NA];
__device__ int   g_flag;

__device__ __forceinline__ unsigned ordkey(float f) {
    unsigned u = __float_as_uint(f);
    return (u & 0x80000000u) ? ~u : (u | 0x80000000u);
}
#define ORD_NEG_INF 0x007FFFFFu

__device__ __forceinline__ float to_tf32(float v) {
    float r;
    asm("cvt.rna.tf32.f32 %0, %1;" : "=f"(r) : "f"(v));
    return r;
}

#define MMA_TF32(c, a, b) \
    asm volatile("mma.sync.aligned.m16n8k8.row.col.f32.tf32.tf32.f32 " \
        "{%0,%1,%2,%3}, {%4,%5,%6,%7}, {%8,%9}, {%0,%1,%2,%3};" \
        : "+f"((c)[0]), "+f"((c)[1]), "+f"((c)[2]), "+f"((c)[3]) \
        : "r"((a).x), "r"((a).y), "r"((a).z), "r"((a).w), \
          "r"((b)[0]), "r"((b)[1]))

// ---- packed f32x2 helpers (fallback conv) ----
__device__ __forceinline__ unsigned long long bc2(float f) {
    unsigned long long r; unsigned u = __float_as_uint(f);
    asm("mov.b64 %0, {%1, %1};" : "=l"(r) : "r"(u));
    return r;
}
#define FMA2(d, a, b, c) \
    asm("fma.rn.f32x2 %0, %1, %2, %3;" : "=l"(d) : "l"(a), "l"(b), "l"(c))
__device__ __forceinline__ float lo32(unsigned long long v) {
    return __uint_as_float((unsigned)v);
}
__device__ __forceinline__ float hi32(unsigned long long v) {
    return __uint_as_float((unsigned)(v >> 32));
}

__global__ void zero_flag_kernel() { g_flag = 0; }

// ======================= mma path pre-passes ==================================
// ROUND-9 VARIANT: A-fragment register order hypothesis B:
//   reg0:(m, k)  reg1:(m, k+4)  reg2:(m+8, k)  reg3:(m+8, k+4)
__global__ __launch_bounds__(256) void prep_w_tc(const float* __restrict__ Wc)
{
    int idx = blockIdx.x * 256 + threadIdx.x;
    if (idx >= 4 * NKK8 * 8 * 32 * 4) return;
    int r   = idx & 3;
    int lam = (idx >> 2) & 31;
    int mf  = (idx >> 7) & 7;
    int rest = idx >> 10;
    int kk8 = rest % NKK8;
    int mt  = rest / NKK8;
    int oc = mt * 128 + mf * 16 + (lam >> 2) + (r >> 1) * 8;   // row+8 on reg pair
    int t  = kk8 / 128;
    int ic = (kk8 % 128) * 8 + (lam & 3) + (r & 1) * 4;        // k+4 on reg parity
    float v  = Wc[((size_t)oc * IC + ic) * 9 + t];
    float a0 = to_tf32(v);
    float r1 = v - a0;
    float a1 = to_tf32(r1);
    float a2 = to_tf32(r1 - a1);
    size_t base = (size_t)(mt * NKK8 + kk8) * 3072 + mf * 128 + lam * 4 + r;
    g_wtc[base]        = a0;
    g_wtc[base + 1024] = a1;
    g_wtc[base + 2048] = a2;
}

__global__ __launch_bounds__(256) void prep_x_tc(const float* __restrict__ in)
{
    int idx = blockIdx.x * 256 + threadIdx.x;
    if (idx >= NB * 66 * 66 * 1024) return;
    int ic = idx & 1023;
    int pix = idx >> 10;
    int pc = pix % 66;
    int rest2 = pix / 66;
    int pr = rest2 % 66;
    int b  = rest2 / 66;
    int h = pr - 1, w = pc - 1;
    float v = 0.f;
    if (h >= 0 && h < HH && w >= 0 && w < WWW)
        v = in[(((size_t)b * IC + ic) * HH + h) * WWW + w];
    float a0 = to_tf32(v);
    float r1 = v - a0;
    float a1 = to_tf32(r1);
    float a2 = to_tf32(r1 - a1);
    size_t base = (size_t)pix * 3072 + ic;
    g_xs3[base]        = a0;
    g_xs3[base + 1024] = a1;
    g_xs3[base + 2048] = a2;
}

// ====================== mma conv (under test) =================================
__global__ __launch_bounds__(256, 1) void conv_mma_kernel(const float* __restrict__ bc)
{
    extern __shared__ char smem[];
    const int tid  = threadIdx.x;
    const int wid  = tid >> 5;
    const int lane = tid & 31;
    const int mt = blockIdx.x;
    const int nt = blockIdx.y;
    const int b  = blockIdx.z;
    const int h0 = nt * 2;
    const int wm = wid & 1;
    const int wn = wid >> 1;

    float acc[4][4][4];
#pragma unroll
    for (int i = 0; i < 4; i++)
#pragma unroll
        for (int j = 0; j < 4; j++)
#pragma unroll
            for (int r = 0; r < 4; r++) acc[i][j][r] = 0.f;

    const char*  wsrc = (const char*)(g_wtc + (size_t)mt * NKK8 * 3072);
    const float* xb   = g_xs3 + (size_t)b * 66 * 66 * 3072;

    int bl_n[12], bl_u[12], bl_s[12];
#pragma unroll
    for (int j = 0; j < 12; j++) {
        int id = tid + j * 256;
        bl_s[j] = id >> 10;
        bl_n[j] = (id >> 3) & 127;
        bl_u[j] = id & 7;
    }

    auto issue = [&](int i, int st) {
        char* sa = smem + st * STAGE_BYTES;
        const char* asrc = wsrc + (size_t)i * 49152;
        unsigned au = (unsigned)__cvta_generic_to_shared(sa);
#pragma unroll
        for (int j = 0; j < 12; j++) {
            int off = (tid + j * 256) * 16;
            asm volatile("cp.async.cg.shared.global [%0], [%1], 16;"
                         :: "r"(au + off), "l"(asrc + off));
        }
        int t = i >> 5, c32 = i & 31;
        int kh = t / 3, kw = t - kh * 3;
        unsigned bu = au + B_OFF;
#pragma unroll
        for (int j = 0; j < 12; j++) {
            int n = bl_n[j];
            int pr = h0 + (n >> 6) + kh;
            int pc = (n & 63) + kw;
            const float* src = xb + (size_t)(pr * 66 + pc) * 3072 + (bl_s[j] << 10)
                                  + (c32 << 5) + (bl_u[j] << 2);
            unsigned dst = bu + bl_s[j] * 18432 + n * 144 + bl_u[j] * 16;
            asm volatile("cp.async.cg.shared.global [%0], [%1], 16;"
                         :: "r"(dst), "l"(src));
        }
        asm volatile("cp.async.commit_group;");
    };

    issue(0, 0);

    for (int i = 0; i < NITER; i++) {
        const int st = i & 1;
        if (i + 1 < NITER) {
            issue(i + 1, st ^ 1);
            asm volatile("cp.async.wait_group 1;");
        } else {
            asm volatile("cp.async.wait_group 0;");
        }
        __syncthreads();

        const char* sa = smem + st * STAGE_BYTES;
#pragma unroll
        for (int kk8 = 0; kk8 < 4; kk8++) {
            uint4 a[3][4];
#pragma unroll
            for (int s = 0; s < 3; s++)
#pragma unroll
                for (int mf = 0; mf < 4; mf++)
                    a[s][mf] = *(const uint4*)(sa +
                        (((kk8 * 3 + s) * 8 + (wm * 4 + mf)) * 512) + lane * 16);
            uint32_t bb[3][4][2];
#pragma unroll
            for (int s = 0; s < 3; s++)
#pragma unroll
                for (int nf = 0; nf < 4; nf++) {
                    const char* ba = sa + B_OFF + s * 18432
                        + (wn * 32 + nf * 8 + (lane >> 2)) * 144
                        + (kk8 * 8 + (lane & 3)) * 4;
                    bb[s][nf][0] = *(const uint32_t*)ba;
                    bb[s][nf][1] = *(const uint32_t*)(ba + 16);
                }
#pragma unroll
            for (int mf = 0; mf < 4; mf++)
#pragma unroll
                for (int nf = 0; nf < 4; nf++) {
                    MMA_TF32(acc[mf][nf], a[0][mf], bb[0][nf]);
                    MMA_TF32(acc[mf][nf], a[0][mf], bb[1][nf]);
                    MMA_TF32(acc[mf][nf], a[1][mf], bb[0][nf]);
                    MMA_TF32(acc[mf][nf], a[1][mf], bb[1][nf]);
                    MMA_TF32(acc[mf][nf], a[0][mf], bb[2][nf]);
                    MMA_TF32(acc[mf][nf], a[2][mf], bb[0][nf]);
                }
        }
        __syncthreads();
    }

#pragma unroll
    for (int mf = 0; mf < 4; mf++) {
        int oc0 = mt * 128 + wm * 64 + mf * 16 + (lane >> 2);
        float bias0 = bc[oc0];
        float bias8 = bc[oc0 + 8];
#pragma unroll
        for (int nf = 0; nf < 4; nf++) {
            int nl = wn * 32 + nf * 8 + (lane & 3) * 2;
            int h = h0 + (nl >> 6);
            int w = nl & 63;
            float2 v0, v1;
            v0.x = fmaxf(acc[mf][nf][0] + bias0, 0.f);
            v0.y = fmaxf(acc[mf][nf][1] + bias0, 0.f);
            v1.x = fmaxf(acc[mf][nf][2] + bias8, 0.f);
            v1.y = fmaxf(acc[mf][nf][3] + bias8, 0.f);
            *(float2*)(g_x + (((size_t)(b * OC + oc0) * HH + h) * WWW + w))     = v0;
            *(float2*)(g_x + (((size_t)(b * OC + oc0 + 8) * HH + h) * WWW + w)) = v1;
        }
    }
}

// ============ check kernel: sampled direct fp32 conv vs g_x ===================
__global__ __launch_bounds__(128) void check_kernel(
    const float* __restrict__ in, const float* __restrict__ Wc,
    const float* __restrict__ bc)
{
    __shared__ float part[128];
    const int oc = blockIdx.x, b = blockIdx.y, tid = threadIdx.x;
    const int p = tid & 15, slice = tid >> 4;
    const int hs[4] = {0, 1, 31, 63};
    const int ws[4] = {0, 1, 32, 63};
    const int h = hs[p >> 2], w = ws[p & 3];

    float s = 0.f;
    const float* wrow0 = Wc + (size_t)oc * IC * 9;
    for (int ic = slice * 128; ic < slice * 128 + 128; ic++) {
        const float* wrow = wrow0 + (size_t)ic * 9;
        const float* irow = in + ((size_t)(b * IC + ic) * HH) * WWW;
#pragma unroll
        for (int kh = 0; kh < 3; kh++) {
            int ih = h - 1 + kh;
            if (ih < 0 || ih >= HH) continue;
#pragma unroll
            for (int kw = 0; kw < 3; kw++) {
                int iw = w - 1 + kw;
                if (iw < 0 || iw >= WWW) continue;
                s += wrow[kh * 3 + kw] * irow[ih * WWW + iw];
            }
        }
    }
    part[tid] = s;
    __syncthreads();
    if (tid < 16) {
        float tot = 0.f;
        for (int sl = 0; sl < 8; sl++) tot += part[sl * 16 + tid];
        float v = fmaxf(tot + bc[oc], 0.f);
        float ref = g_x[(((size_t)(b * OC + oc) * HH) + h) * WWW + w];
        float rel = fabsf(v - ref) / fmaxf(fabsf(v), 1.0f);
        if (rel > 1e-4f) atomicOr(&g_flag, 1);
    }
}

// ================= fallback path (round-3 validated, gated) ===================
__global__ __launch_bounds__(256) void prep_weights(const float* __restrict__ Wc)
{
    if (g_flag == 0) return;
    int idx = blockIdx.x * 256 + threadIdx.x;
    if (idx >= NCHUNK * NOCT * WNUM) return;
    int c  = idx / (NOCT * WNUM);
    int r  = idx - c * (NOCT * WNUM);
    int ot = r / WNUM;
    int e  = r - ot * WNUM;
    int icl = e / 288;
    int e2  = e - icl * 288;
    int k   = e2 >> 5;
    int ocl = e2 & 31;
    g_wr[idx] = Wc[((size_t)(ot * 32 + ocl) * IC + c * ICC + icl) * 9 + k];
}

__global__ __launch_bounds__(256) void prep_input(const float* __restrict__ in)
{
    if (g_flag == 0) return;
    int idx = blockIdx.x * 256 + threadIdx.x;
    const int TOT = NB * IC * 66 * IPITCH;
    if (idx >= TOT) return;
    int bi  = idx / (66 * IPITCH);
    int r   = idx - bi * (66 * IPITCH);
    int row = r / IPITCH;
    int col = r - row * IPITCH;
    int h   = row - 1;
    int w   = col - 1;
    float v = 0.f;
    if (h >= 0 && h < HH && w >= 0 && w < WWW && col < 66)
        v = in[((size_t)bi * HH + h) * WWW + w];
    g_ipad[idx] = v;
}

__global__ __launch_bounds__(128, 3) void conv_ffma2_kernel(const float* __restrict__ bc)
{
    if (g_flag == 0) return;
    __shared__ float sW[2][WNUM];
    __shared__ float sIn[2][INUM];

    const int oc0 = blockIdx.x * OCT;
    const int h0  = blockIdx.y * HT;
    const int b   = blockIdx.z;
    const int tid = threadIdx.x;

    const int tz  = tid >> 5;
    const int to0 = ((tid >> 3) & 3) * 8;
    const int tw0 = (tid & 7) * 8;

    const unsigned sW_u[2] = {
        (unsigned)__cvta_generic_to_shared(&sW[0][0]),
        (unsigned)__cvta_generic_to_shared(&sW[1][0]) };
    const unsigned sIn_u[2] = {
        (unsigned)__cvta_generic_to_shared(&sIn[0][0]),
        (unsigned)__cvta_generic_to_shared(&sIn[1][0]) };

    const float* wbase = g_wr + (size_t)blockIdx.x * WNUM;
    int i_icl[7], i_off[7];
#pragma unroll
    for (int s = 0; s < 7; s++) {
        int idx4 = tid + s * 128;
        int icl  = idx4 / 102;
        int r    = idx4 - icl * 102;
        int row  = r / 17;
        int c4   = r - row * 17;
        i_icl[s] = icl;
        i_off[s] = (h0 + row) * IPITCH + c4 * 4;
    }

    unsigned long long acc2[4][8];
#pragma unroll
    for (int p = 0; p < 4; p++)
#pragma unroll
        for (int j = 0; j < 8; j++) acc2[p][j] = 0ull;

    auto issue_chunk = [&](int kc, int bu) {
        const unsigned sWu  = sW_u[bu];
        const unsigned sInu = sIn_u[bu];
        const float* ws = wbase + (size_t)kc * (NOCT * WNUM);
#pragma unroll
        for (int s = 0; s < 5; s++) {
            int idx4 = tid + s * 128;
            if (idx4 < WNUM / 4) {
                const float* g = ws + idx4 * 4;
                asm volatile("cp.async.cg.shared.global [%0], [%1], 16;"
                             :: "r"(sWu + (unsigned)(idx4 * 16)), "l"(g));
            }
        }
        const int ic0 = kc * ICC;
#pragma unroll
        for (int s = 0; s < 7; s++) {
            int idx4 = tid + s * 128;
            if (idx4 < INUM / 4) {
                const float* g = g_ipad +
                    ((size_t)(b * IC + ic0 + i_icl[s]) * 66) * IPITCH + i_off[s];
                asm volatile("cp.async.cg.shared.global [%0], [%1], 16;"
                             :: "r"(sInu + (unsigned)(idx4 * 16)), "l"(g));
            }
        }
        asm volatile("cp.async.commit_group;");
    };

    issue_chunk(0, 0);

    for (int kc = 0; kc < NCHUNK; kc++) {
        const int cur = kc & 1;
        if (kc < NCHUNK - 1) {
            issue_chunk(kc + 1, cur ^ 1);
            asm volatile("cp.async.wait_group 1;");
        } else {
            asm volatile("cp.async.wait_group 0;");
        }
        __syncthreads();

        const float* W_ = sW[cur];
        const float* I_ = sIn[cur];

#pragma unroll 1
        for (int ic = 0; ic < ICC; ic++) {
            const float* irow = I_ + (ic * 6 + tz) * IPITCH + tw0;
            const float* wrow = W_ + ic * 9 * OCT + to0;
#pragma unroll
            for (int kh = 0; kh < 3; kh++) {
                float4 f0 = *(const float4*)(irow + kh * IPITCH);
                float4 f1 = *(const float4*)(irow + kh * IPITCH + 4);
                float4 f2 = *(const float4*)(irow + kh * IPITCH + 8);
                unsigned long long ib[10];
                ib[0] = bc2(f0.x); ib[1] = bc2(f0.y); ib[2] = bc2(f0.z); ib[3] = bc2(f0.w);
                ib[4] = bc2(f1.x); ib[5] = bc2(f1.y); ib[6] = bc2(f1.z); ib[7] = bc2(f1.w);
                ib[8] = bc2(f2.x); ib[9] = bc2(f2.y);
#pragma unroll
                for (int kw = 0; kw < 3; kw++) {
                    const ulonglong2* wp =
                        (const ulonglong2*)(wrow + (kh * 3 + kw) * OCT);
                    ulonglong2 wa = wp[0];
                    ulonglong2 wb = wp[1];
#pragma unroll
                    for (int j = 0; j < 8; j++) {
                        FMA2(acc2[0][j], wa.x, ib[j + kw], acc2[0][j]);
                        FMA2(acc2[1][j], wa.y, ib[j + kw], acc2[1][j]);
                        FMA2(acc2[2][j], wb.x, ib[j + kw], acc2[2][j]);
                        FMA2(acc2[3][j], wb.y, ib[j + kw], acc2[3][j]);
                    }
                }
            }
        }
        __syncthreads();
    }

    const int h = h0 + tz;
#pragma unroll
    for (int p = 0; p < 4; p++) {
#pragma unroll
        for (int s = 0; s < 2; s++) {
            int oc = oc0 + to0 + 2 * p + s;
            float bias = bc[oc];
            float* op = &g_x[((size_t)(b * OC + oc) * HH + h) * WWW + tw0];
#pragma unroll
            for (int j = 0; j < 8; j++) {
                float v = (s == 0 ? lo32(acc2[p][j]) : hi32(acc2[p][j])) + bias;
                op[j] = v > 0.f ? v : 0.f;
            }
        }
    }
}

// ============ Kernel 2: heads (round-3 validated 64-thread version) ===========
__global__ __launch_bounds__(64) void heads_kernel(
    const float* __restrict__ meta,
    const float* __restrict__ Wcls, const float* __restrict__ bcls,
    const float* __restrict__ Wbb,  const float* __restrict__ bbb)
{
    __shared__ float sw[512 * 20];
    __shared__ float sb[20];

    const int h = blockIdx.x, b = blockIdx.y, tid = threadIdx.x;

    for (int idx = tid; idx < 512 * 20; idx += 64) {
        int c = idx / 20, o = idx - c * 20;
        sw[idx] = (o < 4) ? Wcls[o * 512 + c] : Wbb[(o - 4) * 512 + c];
    }
    if (tid < 20) sb[tid] = (tid < 4) ? bcls[tid] : bbb[tid - 4];
    __syncthreads();

    const int w = tid;
    float acc[20];
#pragma unroll
    for (int o = 0; o < 20; o++) acc[o] = 0.f;

    const float* xp = g_x + ((size_t)(b * OC) * HH + h) * WWW + w;
    for (int c = 0; c < 512; c++) {
        float xv = xp[(size_t)c * HH * WWW];
        const float4* wp = reinterpret_cast<const float4*>(&sw[c * 20]);
        float4 w0 = wp[0], w1 = wp[1], w2 = wp[2], w3 = wp[3], w4 = wp[4];
        acc[0]  = fmaf(xv, w0.x, acc[0]);  acc[1]  = fmaf(xv, w0.y, acc[1]);
        acc[2]  = fmaf(xv, w0.z, acc[2]);  acc[3]  = fmaf(xv, w0.w, acc[3]);
        acc[4]  = fmaf(xv, w1.x, acc[4]);  acc[5]  = fmaf(xv, w1.y, acc[5]);
        acc[6]  = fmaf(xv, w1.z, acc[6]);  acc[7]  = fmaf(xv, w1.w, acc[7]);
        acc[8]  = fmaf(xv, w2.x, acc[8]);  acc[9]  = fmaf(xv, w2.y, acc[9]);
        acc[10] = fmaf(xv, w2.z, acc[10]); acc[11] = fmaf(xv, w2.w, acc[11]);
        acc[12] = fmaf(xv, w3.x, acc[12]); acc[13] = fmaf(xv, w3.y, acc[13]);
        acc[14] = fmaf(xv, w3.z, acc[14]); acc[15] = fmaf(xv, w3.w, acc[15]);
        acc[16] = fmaf(xv, w4.x, acc[16]); acc[17] = fmaf(xv, w4.y, acc[17]);
        acc[18] = fmaf(xv, w4.z, acc[18]); acc[19] = fmaf(xv, w4.w, acc[19]);
    }

    float s[4];
#pragma unroll
    for (int a = 0; a < 4; a++) s[a] = acc[a] + sb[a];
    float prob[4];
#pragma unroll
    for (int a = 0; a < 4; a++) {
        int p = a ^ 2;
        float m  = fmaxf(s[a], s[p]);
        float ea = expf(s[a] - m);
        float eb = expf(s[p] - m);
        prob[a]  = ea / (ea + eb);
    }

    const float im_h = meta[b * 3 + 0];
    const float im_w = meta[b * 3 + 1];
    const float scl  = meta[b * 3 + 2];
    const float minsz = 16.f * scl;

    const int base = b * NA + (h * 64 + w) * 4;
#pragma unroll
    for (int a = 0; a < 4; a++) {
        float wa = (float)(64 << a);
        float cx = w * 16.f + 8.f;
        float cy = h * 16.f + 8.f;
        float d0 = acc[4 + a * 4 + 0] + sb[4 + a * 4 + 0];
        float d1 = acc[4 + a * 4 + 1] + sb[4 + a * 4 + 1];
        float d2 = acc[4 + a * 4 + 2] + sb[4 + a * 4 + 2];
        float d3 = acc[4 + a * 4 + 3] + sb[4 + a * 4 + 3];
        float pcx = d0 * wa + cx, pcy = d1 * wa + cy;
        float pw  = expf(d2) * wa, ph = expf(d3) * wa;
        float x1 = pcx - 0.5f * pw, y1 = pcy - 0.5f * ph;
        float x2 = pcx + 0.5f * pw, y2 = pcy + 0.5f * ph;
        x1 = fminf(fmaxf(x1, 0.f), im_w - 1.f);
        x2 = fminf(fmaxf(x2, 0.f), im_w - 1.f);
        y1 = fminf(fmaxf(y1, 0.f), im_h - 1.f);
        y2 = fminf(fmaxf(y2, 0.f), im_h - 1.f);
        bool keep = (x2 - x1 + 1.f >= minsz) && (y2 - y1 + 1.f >= minsz);
        g_scores[base + a] = keep ? prob[a] : -INFINITY;
        g_boxes[base + a]  = make_float4(x1, y1, x2, y2);
    }
}

// ================= Kernel 3: exact top-6000 mark (per image) ==================
__global__ __launch_bounds__(1024) void topk_kernel()
{
    const int b   = blockIdx.x;
    const int tid = threadIdx.x;
    float* scores = g_scores + b * NA;

    unsigned key[16];
    const int i0 = tid * 16;
#pragma unroll
    for (int i = 0; i < 16; i++) key[i] = ordkey(scores[i0 + i]);

    __shared__ int wsum[32];
    __shared__ int s_total;
    const int lane = tid & 31, wid = tid >> 5;

    auto count_ge = [&](unsigned cand) -> int {
        int local = 0;
#pragma unroll
        for (int i = 0; i < 16; i++) local += (key[i] >= cand) ? 1 : 0;
        for (int off = 16; off; off >>= 1)
            local += __shfl_down_sync(0xFFFFFFFFu, local, off);
        if (lane == 0) wsum[wid] = local;
        __syncthreads();
        if (tid == 0) {
            int st = 0;
            for (int k = 0; k < 32; k++) st += wsum[k];
            s_total = st;
        }
        __syncthreads();
        int r = s_total;
        __syncthreads();
        return r;
    };

    unsigned thr = 0;
    for (int bit = 31; bit >= 0; bit--) {
        unsigned cand = thr | (1u << bit);
        if (count_ge(cand) >= PRE_NMS_K) thr = cand;
    }
    const int n_gt = count_ge(thr + 1u);
    const int need = PRE_NMS_K - n_gt;

    int my_eq = 0;
#pragma unroll
    for (int i = 0; i < 16; i++) my_eq += (key[i] == thr) ? 1 : 0;

    int v = my_eq;
    for (int off = 1; off < 32; off <<= 1) {
        int tt = __shfl_up_sync(0xFFFFFFFFu, v, off);
        if (lane >= off) v += tt;
    }
    __syncthreads();
    if (lane == 31) wsum[wid] = v;
    __syncthreads();
    if (wid == 0) {
        int sv = wsum[lane];
        for (int off = 1; off < 32; off <<= 1) {
            int tt = __shfl_up_sync(0xFFFFFFFFu, sv, off);
            if (lane >= off) sv += tt;
        }
        wsum[lane] = sv;
    }
    __syncthreads();
    int rank = v - my_eq + (wid ? wsum[wid - 1] : 0);

#pragma unroll
    for (int i = 0; i < 16; i++) {
        if (key[i] == thr) {
            if (rank >= need) scores[i0 + i] = -INFINITY;
            rank++;
        } else if (key[i] < thr) {
            scores[i0 + i] = -INFINITY;
        }
    }
}

// ===================== Kernel 4: exact greedy NMS (per image) =================
__global__ __launch_bounds__(512) void nms_kernel(float* __restrict__ out)
{
    const int b   = blockIdx.x;
    const int tid = threadIdx.x;
    const float4* boxes = g_boxes + b * NA;

    float sc[32];
    const int i0 = tid * 32;
#pragma unroll
    for (int i = 0; i < 32; i++) sc[i] = g_scores[b * NA + i0 + i];

    __shared__ unsigned long long swm[16];
    __shared__ unsigned long long s_best;
    __shared__ float4 s_box;
    __shared__ float  s_area;
    __shared__ int    s_firstj;

    const int lane = tid & 31, wid = tid >> 5;

    for (int it = 0; it < POST_NMS_K; it++) {
        unsigned long long loc = ((unsigned long long)ORD_NEG_INF << 32);
#pragma unroll
        for (int i = 0; i < 32; i++) {
            unsigned long long kk =
                ((unsigned long long)ordkey(sc[i]) << 32) |
                (unsigned)(65535 - (i0 + i));
            loc = (kk > loc) ? kk : loc;
        }
        for (int off = 16; off; off >>= 1) {
            unsigned long long o = __shfl_down_sync(0xFFFFFFFFu, loc, off);
            loc = (o > loc) ? o : loc;
        }
        if (lane == 0) swm[wid] = loc;
        __syncthreads();
        if (tid < 16) {
            unsigned long long vv = swm[tid];
            for (int off = 8; off; off >>= 1) {
                unsigned long long o = __shfl_down_sync(0x0000FFFFu, vv, off);
                vv = (o > vv) ? o : vv;
            }
            if (tid == 0) s_best = vv;
        }
        __syncthreads();

        if (tid == 0) {
            unsigned long long best = s_best;
            unsigned keypart = (unsigned)(best >> 32);
            int j;
            if (keypart == ORD_NEG_INF && it > 0) j = s_firstj;
            else j = 65535 - (int)(best & 0xFFFFFFFFull);
            if (it == 0) s_firstj = j;
            float4 bx = boxes[j];
            s_box  = bx;
            s_area = (bx.z - bx.x + 1.f) * (bx.w - bx.y + 1.f);
            float* o = out + (size_t)(b * POST_NMS_K + it) * 5;
            o[0] = (float)b; o[1] = bx.x; o[2] = bx.y; o[3] = bx.z; o[4] = bx.w;
        }
        __syncthreads();

        const float4 jb = s_box;
        const float  ja = s_area;
#pragma unroll 4
        for (int i = 0; i < 32; i++) {
            float4 bb = boxes[i0 + i];
            float xx1 = fmaxf(jb.x, bb.x);
            float yy1 = fmaxf(jb.y, bb.y);
            float xx2 = fminf(jb.z, bb.z);
            float yy2 = fminf(jb.w, bb.w);
            float iw  = fmaxf(xx2 - xx1 + 1.f, 0.f);
            float ih  = fmaxf(yy2 - yy1 + 1.f, 0.f);
            float inter = iw * ih;
            float area  = (bb.z - bb.x + 1.f) * (bb.w - bb.y + 1.f);
            float iou   = inter / (ja + area - inter);
            if (iou > 0.7f) sc[i] = -INFINITY;
        }
    }
}

// ================================ launcher ====================================
extern "C" void kernel_launch(void* const* d_in, const int* in_sizes, int n_in,
                              void* d_out, int out_size)
{
    const float* feat = (const float*)d_in[0];
    const float* meta = (const float*)d_in[1];
    const float* Wc   = (const float*)d_in[3];
    const float* bc   = (const float*)d_in[4];
    const float* Wcls = (const float*)d_in[5];
    const float* bcls = (const float*)d_in[6];
    const float* Wbb  = (const float*)d_in[7];
    const float* bbb  = (const float*)d_in[8];
    float* out = (float*)d_out;

    cudaFuncSetAttribute(conv_mma_kernel,
                         cudaFuncAttributeMaxDynamicSharedMemorySize, CONV_SMEM);

    zero_flag_kernel<<<1, 1>>>();
    // --- mma path, A-fragment ordering variant B ---
    prep_w_tc<<<(4 * NKK8 * 1024 + 255) / 256, 256>>>(Wc);
    prep_x_tc<<<(NB * 66 * 66 * 1024 + 255) / 256, 256>>>(feat);
    conv_mma_kernel<<<dim3(4, 32, 2), 256, CONV_SMEM>>>(bc);
    // --- verify samples; set g_flag if mma conv is wrong ---
    check_kernel<<<dim3(512, 2), 128>>>(feat, Wc, bc);
    // --- validated fallback path (runs only if flag set) ---
    prep_weights<<<(NCHUNK * NOCT * WNUM + 255) / 256, 256>>>(Wc);
    prep_input<<<(NB * IC * 66 * IPITCH + 255) / 256, 256>>>(feat);
    conv_ffma2_kernel<<<dim3(16, 16, 2), 128>>>(bc);
    // --- validated tail ---
    heads_kernel<<<dim3(64, 2), 64>>>(meta, Wcls, bcls, Wbb, bbb);
    topk_kernel<<<2, 1024>>>();
    nms_kernel<<<2, 512>>>(out);
}